// round 8
// baseline (speedup 1.0000x reference)
#include <cuda_runtime.h>
#include <cuda_bf16.h>
#include <cstdint>

#define N_NODES 100000
#define F_IN    512
#define HID     256
#define N_CLS   32
#define N_EDGES 3200000
#define KSTEPS  10
#define NBLK    ((N_NODES + 255) / 256)   // 391

// ---------------- device scratch ----------------
__device__ __align__(128) float g_h0[(size_t)N_NODES * N_CLS];   // p ping
__device__ __align__(128) float g_h1[(size_t)N_NODES * N_CLS];   // p pong
__device__ __align__(128) float g_acc[(size_t)N_NODES * N_CLS];
__device__ __align__(128) int   g_deg[N_NODES];
__device__ __align__(128) int   g_rowptr[N_NODES + 1];
__device__ __align__(128) int   g_pos[N_NODES];
__device__ __align__(128) int   g_srcv[N_EDGES];
__device__ __align__(128) int   g_dstv[N_EDGES];
__device__ __align__(128) int   g_csr_idx[N_EDGES];
__device__ __align__(128) int   g_bsum[512];
__device__ __align__(128) int   g_boff[512];
__device__ __align__(128) __nv_bfloat16 g_w1t_hi[(size_t)HID * F_IN];
__device__ __align__(128) __nv_bfloat16 g_w1t_lo[(size_t)HID * F_IN];
__device__ __align__(128) __nv_bfloat16 g_w2t_hi[(size_t)N_CLS * HID];
__device__ __align__(128) __nv_bfloat16 g_w2t_lo[(size_t)N_CLS * HID];
__device__ int g_is64;

// ---------------- edge index dtype sniff + convert (+deg count fused) ----------------
__global__ void k_sniff(const unsigned* __restrict__ raw) {
    unsigned orv = 0;
#pragma unroll
    for (int i = 0; i < 16; i++) orv |= raw[2 * i + 1];
    g_is64 = (orv == 0u) ? 1 : 0;
}

__global__ void k_cvt(const void* __restrict__ raw) {
    int i = blockIdx.x * blockDim.x + threadIdx.x;
    if (i >= 2 * N_EDGES) return;
    int v;
    if (g_is64) v = (int)((const long long*)raw)[i];
    else        v = ((const int*)raw)[i];
    if (i < N_EDGES) g_srcv[i] = v;
    else { g_dstv[i - N_EDGES] = v; atomicAdd(&g_deg[v], 1); }
}

__global__ void k_deg_zero() {
    int i = blockIdx.x * blockDim.x + threadIdx.x;
    if (i < N_NODES) g_deg[i] = 0;
}

// ---------------- parallel exclusive scan of g_deg -> g_rowptr/g_pos ----------------
__global__ __launch_bounds__(256) void k_scan1() {
    __shared__ int wsum[8];
    int tid = threadIdx.x;
    int i = blockIdx.x * 256 + tid;
    int v = (i < N_NODES) ? g_deg[i] : 0;
    int x = v;
#pragma unroll
    for (int o = 16; o; o >>= 1) x += __shfl_down_sync(0xffffffffu, x, o);
    if ((tid & 31) == 0) wsum[tid >> 5] = x;
    __syncthreads();
    if (tid < 8) {
        int y = wsum[tid];
#pragma unroll
        for (int o = 4; o; o >>= 1) y += __shfl_down_sync(0xffu, y, o);
        if (tid == 0) g_bsum[blockIdx.x] = y;
    }
}

__global__ __launch_bounds__(512) void k_scan2() {
    __shared__ int wsum[16];
    int tid = threadIdx.x;
    int lane = tid & 31, w = tid >> 5;
    int v = (tid < NBLK) ? g_bsum[tid] : 0;
    int x = v;
#pragma unroll
    for (int o = 1; o < 32; o <<= 1) {
        int t = __shfl_up_sync(0xffffffffu, x, o);
        if (lane >= o) x += t;
    }
    if (lane == 31) wsum[w] = x;
    __syncthreads();
    if (tid < 16) {
        int y = wsum[tid];
#pragma unroll
        for (int o = 1; o < 16; o <<= 1) {
            int t = __shfl_up_sync(0xffffu, y, o);
            if (tid >= o) y += t;
        }
        wsum[tid] = y;
    }
    __syncthreads();
    int pre = (w > 0) ? wsum[w - 1] : 0;
    int excl = pre + x - v;
    g_boff[tid] = excl;
    if (tid == NBLK) g_rowptr[N_NODES] = excl;
}

__global__ __launch_bounds__(256) void k_scan3() {
    __shared__ int wsum[8];
    int tid = threadIdx.x;
    int i = blockIdx.x * 256 + tid;
    int lane = tid & 31, w = tid >> 5;
    int v = (i < N_NODES) ? g_deg[i] : 0;
    int x = v;
#pragma unroll
    for (int o = 1; o < 32; o <<= 1) {
        int t = __shfl_up_sync(0xffffffffu, x, o);
        if (lane >= o) x += t;
    }
    if (lane == 31) wsum[w] = x;
    __syncthreads();
    if (tid < 8) {
        int y = wsum[tid];
#pragma unroll
        for (int o = 1; o < 8; o <<= 1) {
            int t = __shfl_up_sync(0xffu, y, o);
            if (tid >= o) y += t;
        }
        wsum[tid] = y;
    }
    __syncthreads();
    int pre = (w > 0) ? wsum[w - 1] : 0;
    int excl = g_boff[blockIdx.x] + pre + x - v;
    if (i < N_NODES) { g_rowptr[i] = excl; g_pos[i] = excl; }
}

__global__ void k_fill() {
    int e = blockIdx.x * blockDim.x + threadIdx.x;
    if (e >= N_EDGES) return;
    int s = g_srcv[e], d = g_dstv[e];
    int p = atomicAdd(&g_pos[d], 1);
    g_csr_idx[p] = s;
}

// ---------------- weight conversions ----------------
__global__ void k_w1cvt(const float* __restrict__ W1) {
    int i = blockIdx.x * blockDim.x + threadIdx.x;
    if (i >= F_IN * HID) return;
    int k = i / HID, n = i % HID;
    float v = W1[i];
    __nv_bfloat16 h = __float2bfloat16(v);
    g_w1t_hi[(size_t)n * F_IN + k] = h;
    g_w1t_lo[(size_t)n * F_IN + k] = __float2bfloat16(v - __bfloat162float(h));
}

__global__ void k_w2cvt(const float* __restrict__ W2) {
    int i = blockIdx.x * blockDim.x + threadIdx.x;
    if (i >= HID * N_CLS) return;
    int k = i / N_CLS, n = i % N_CLS;
    float v = W2[i];
    __nv_bfloat16 h = __float2bfloat16(v);
    g_w2t_hi[(size_t)n * HID + k] = h;
    g_w2t_lo[(size_t)n * HID + k] = __float2bfloat16(v - __bfloat162float(h));
}

// ---------------- fused MLP: h0 = relu(x@W1+b1)@W2 + b2 ----------------
// stores h0 into g_h0 (unscaled) and acc = gamma0*h0 into g_acc
#define ST1  72
#define ST2  264

#define ASH_O   0u
#define ASL_O   18432u
#define BSH_O   36864u
#define BSL_O   73728u
#define ZHI_O   0u
#define ZLO_O   67584u
#define W2HI_O  135168u
#define W2LO_O  152064u
#define B2_O    168960u
#define BIAS_O  169088u
#define SMEM_T  170112u

#define MMA16816(c, a, b) \
    asm volatile("mma.sync.aligned.m16n8k16.row.col.f32.bf16.bf16.f32 " \
                 "{%0,%1,%2,%3},{%4,%5,%6,%7},{%8,%9},{%0,%1,%2,%3};" \
                 : "+f"((c)[0]), "+f"((c)[1]), "+f"((c)[2]), "+f"((c)[3]) \
                 : "r"((a)[0]), "r"((a)[1]), "r"((a)[2]), "r"((a)[3]), \
                   "r"((b)[0]), "r"((b)[1]))

__device__ __forceinline__ uint32_t pack_hi(float a, float b) {
    __nv_bfloat16 h0 = __float2bfloat16(a), h1 = __float2bfloat16(b);
    return (uint32_t)__bfloat16_as_ushort(h0) | ((uint32_t)__bfloat16_as_ushort(h1) << 16);
}
__device__ __forceinline__ uint32_t pack_lo(float a, float b) {
    __nv_bfloat16 h0 = __float2bfloat16(a), h1 = __float2bfloat16(b);
    float r0 = a - __bfloat162float(h0), r1 = b - __bfloat162float(h1);
    __nv_bfloat16 l0 = __float2bfloat16(r0), l1 = __float2bfloat16(r1);
    return (uint32_t)__bfloat16_as_ushort(l0) | ((uint32_t)__bfloat16_as_ushort(l1) << 16);
}

__global__ __launch_bounds__(256, 1) void k_mlp(const float* __restrict__ x,
                                                const float* __restrict__ b1,
                                                const float* __restrict__ b2,
                                                const float* __restrict__ gamma) {
    extern __shared__ __align__(16) char sm[];
    __nv_bfloat16* as_hi = (__nv_bfloat16*)(sm + ASH_O);
    __nv_bfloat16* as_lo = (__nv_bfloat16*)(sm + ASL_O);
    __nv_bfloat16* bs_hi = (__nv_bfloat16*)(sm + BSH_O);
    __nv_bfloat16* bs_lo = (__nv_bfloat16*)(sm + BSL_O);
    uint32_t* zhi = (uint32_t*)(sm + ZHI_O);
    uint32_t* zlo = (uint32_t*)(sm + ZLO_O);
    __nv_bfloat16* w2hi = (__nv_bfloat16*)(sm + W2HI_O);
    __nv_bfloat16* w2lo = (__nv_bfloat16*)(sm + W2LO_O);
    float* b2s = (float*)(sm + B2_O);
    float* bias_s = (float*)(sm + BIAS_O);

    const int tid = threadIdx.x;
    const int wid = tid >> 5, lane = tid & 31;
    const int gq = lane >> 2, tg = lane & 3;
    const int rowBase = blockIdx.x * 128;
    const int wr = (wid >> 2) * 64, wc = (wid & 3) * 64;

    bias_s[tid] = b1[tid];
    if (tid < N_CLS) b2s[tid] = b2[tid];
    for (int i = tid; i < 1024; i += 256) {
        int n = i >> 5, k8 = (i & 31) * 8;
        *(uint4*)(w2hi + n * ST2 + k8) = *(const uint4*)(g_w2t_hi + n * HID + k8);
        *(uint4*)(w2lo + n * ST2 + k8) = *(const uint4*)(g_w2t_lo + n * HID + k8);
    }

    float acc[4][8][4];
#pragma unroll
    for (int a = 0; a < 4; a++)
#pragma unroll
        for (int b = 0; b < 8; b++)
#pragma unroll
            for (int c = 0; c < 4; c++) acc[a][b][c] = 0.f;

    for (int ch = 0; ch < 8; ch++) {
        const int k0 = ch * 64;
        __syncthreads();
        for (int i = tid; i < 2048; i += 256) {
            int r = i >> 4, cc = (i & 15) * 4;
            float4 v = make_float4(0.f, 0.f, 0.f, 0.f);
            int grow = rowBase + r;
            if (grow < N_NODES)
                v = *(const float4*)(x + (size_t)grow * F_IN + k0 + cc);
            uint2 ph = make_uint2(pack_hi(v.x, v.y), pack_hi(v.z, v.w));
            uint2 pl = make_uint2(pack_lo(v.x, v.y), pack_lo(v.z, v.w));
            *(uint2*)(as_hi + r * ST1 + cc) = ph;
            *(uint2*)(as_lo + r * ST1 + cc) = pl;
        }
        for (int i = tid; i < 2048; i += 256) {
            int n = i >> 3, k8 = (i & 7) * 8;
            size_t gi = (size_t)n * F_IN + k0 + k8;
            *(uint4*)(bs_hi + n * ST1 + k8) = *(const uint4*)(g_w1t_hi + gi);
            *(uint4*)(bs_lo + n * ST1 + k8) = *(const uint4*)(g_w1t_lo + gi);
        }
        __syncthreads();

#pragma unroll
        for (int ks = 0; ks < 4; ks++) {
            const int ko = ks * 16;
            uint32_t ah[4][4], al[4][4];
#pragma unroll
            for (int mt = 0; mt < 4; mt++) {
                int r0 = wr + mt * 16 + gq;
                ah[mt][0] = *(const uint32_t*)(as_hi + r0 * ST1 + ko + 2 * tg);
                ah[mt][1] = *(const uint32_t*)(as_hi + (r0 + 8) * ST1 + ko + 2 * tg);
                ah[mt][2] = *(const uint32_t*)(as_hi + r0 * ST1 + ko + 8 + 2 * tg);
                ah[mt][3] = *(const uint32_t*)(as_hi + (r0 + 8) * ST1 + ko + 8 + 2 * tg);
                al[mt][0] = *(const uint32_t*)(as_lo + r0 * ST1 + ko + 2 * tg);
                al[mt][1] = *(const uint32_t*)(as_lo + (r0 + 8) * ST1 + ko + 2 * tg);
                al[mt][2] = *(const uint32_t*)(as_lo + r0 * ST1 + ko + 8 + 2 * tg);
                al[mt][3] = *(const uint32_t*)(as_lo + (r0 + 8) * ST1 + ko + 8 + 2 * tg);
            }
#pragma unroll
            for (int nt = 0; nt < 8; nt++) {
                int n0 = wc + nt * 8 + gq;
                uint32_t bh[2], bl[2];
                bh[0] = *(const uint32_t*)(bs_hi + n0 * ST1 + ko + 2 * tg);
                bh[1] = *(const uint32_t*)(bs_hi + n0 * ST1 + ko + 8 + 2 * tg);
                bl[0] = *(const uint32_t*)(bs_lo + n0 * ST1 + ko + 2 * tg);
                bl[1] = *(const uint32_t*)(bs_lo + n0 * ST1 + ko + 8 + 2 * tg);
#pragma unroll
                for (int mt = 0; mt < 4; mt++) {
                    MMA16816(acc[mt][nt], ah[mt], bh);
                    MMA16816(acc[mt][nt], ah[mt], bl);
                    MMA16816(acc[mt][nt], al[mt], bh);
                }
            }
        }
    }

    __syncthreads();

    // phase1 epilogue: bias+relu -> z bf16 hi/lo in smem
#pragma unroll
    for (int mt = 0; mt < 4; mt++) {
        int r0 = wr + mt * 16 + gq;
        int r1 = r0 + 8;
#pragma unroll
        for (int nt = 0; nt < 8; nt++) {
            int cl = wc + nt * 8 + 2 * tg;
            float bx = bias_s[cl], by = bias_s[cl + 1];
            float o0 = fmaxf(acc[mt][nt][0] + bx, 0.f);
            float o1 = fmaxf(acc[mt][nt][1] + by, 0.f);
            float o2 = fmaxf(acc[mt][nt][2] + bx, 0.f);
            float o3 = fmaxf(acc[mt][nt][3] + by, 0.f);
            int w0 = r0 * 132 + (cl >> 1);
            int w1 = r1 * 132 + (cl >> 1);
            zhi[w0] = pack_hi(o0, o1); zlo[w0] = pack_lo(o0, o1);
            zhi[w1] = pack_hi(o2, o3); zlo[w1] = pack_lo(o2, o3);
        }
    }
    __syncthreads();

    // phase2: h0 = z @ W2 + b2 ; acc = gamma0*h0
    float acc2[4][4];
#pragma unroll
    for (int a = 0; a < 4; a++)
#pragma unroll
        for (int c = 0; c < 4; c++) acc2[a][c] = 0.f;

    const int rl0 = wid * 16 + gq;
#pragma unroll
    for (int ks = 0; ks < 16; ks++) {
        const int kw = ks * 8 + tg;
        uint32_t ah[4], al[4];
        ah[0] = zhi[rl0 * 132 + kw];
        ah[1] = zhi[(rl0 + 8) * 132 + kw];
        ah[2] = zhi[rl0 * 132 + kw + 4];
        ah[3] = zhi[(rl0 + 8) * 132 + kw + 4];
        al[0] = zlo[rl0 * 132 + kw];
        al[1] = zlo[(rl0 + 8) * 132 + kw];
        al[2] = zlo[rl0 * 132 + kw + 4];
        al[3] = zlo[(rl0 + 8) * 132 + kw + 4];
#pragma unroll
        for (int nt = 0; nt < 4; nt++) {
            int n0 = nt * 8 + gq;
            uint32_t bh[2], bl[2];
            bh[0] = *(const uint32_t*)(w2hi + n0 * ST2 + ks * 16 + 2 * tg);
            bh[1] = *(const uint32_t*)(w2hi + n0 * ST2 + ks * 16 + 8 + 2 * tg);
            bl[0] = *(const uint32_t*)(w2lo + n0 * ST2 + ks * 16 + 2 * tg);
            bl[1] = *(const uint32_t*)(w2lo + n0 * ST2 + ks * 16 + 8 + 2 * tg);
            MMA16816(acc2[nt], ah, bh);
            MMA16816(acc2[nt], ah, bl);
            MMA16816(acc2[nt], al, bh);
        }
    }

    float g0 = gamma[0];
    int row0 = rowBase + rl0, row1 = row0 + 8;
#pragma unroll
    for (int nt = 0; nt < 4; nt++) {
        int cl = nt * 8 + 2 * tg;
        float bx = b2s[cl], by = b2s[cl + 1];
        if (row0 < N_NODES) {
            float hx = acc2[nt][0] + bx, hy = acc2[nt][1] + by;
            *(float2*)(g_h0 + (size_t)row0 * N_CLS + cl) = make_float2(hx, hy);
            *(float2*)(g_acc + (size_t)row0 * N_CLS + cl) = make_float2(g0 * hx, g0 * hy);
        }
        if (row1 < N_NODES) {
            float hx = acc2[nt][2] + bx, hy = acc2[nt][3] + by;
            *(float2*)(g_h0 + (size_t)row1 * N_CLS + cl) = make_float2(hx, hy);
            *(float2*)(g_acc + (size_t)row1 * N_CLS + cl) = make_float2(g0 * hx, g0 * hy);
        }
    }
}

// ---------------- scale: p0 = dinv * h0 (after join; needs deg + h0) ----------------
__global__ void k_scale() {
    int i = blockIdx.x * blockDim.x + threadIdx.x;   // one float4
    if (i >= N_NODES * N_CLS / 4) return;
    int n = i >> 3;
    float di = rsqrtf(1.0f + (float)g_deg[n]);
    float4 v = *(float4*)(g_h0 + (size_t)i * 4);
    v.x *= di; v.y *= di; v.z *= di; v.w *= di;
    *(float4*)(g_h0 + (size_t)i * 4) = v;
}

// ---------------- SpMV step on p = dinv*h ----------------
template <bool LAST>
__global__ __launch_bounds__(256) void k_spmv(int cur, int gi,
                                              const float* __restrict__ gamma,
                                              float* __restrict__ out) {
    __shared__ int est[8][32];
    const float* pc = cur ? g_h1 : g_h0;
    float* pn = cur ? g_h0 : g_h1;

    const int ws = threadIdx.x >> 5;
    int n = (blockIdx.x * blockDim.x + threadIdx.x) >> 5;
    int lane = threadIdx.x & 31;
    if (n >= N_NODES) return;
    int beg = g_rowptr[n], end = g_rowptr[n + 1];
    float acc = pc[(size_t)n * N_CLS + lane];   // self loop

    for (int e0 = beg; e0 < end; e0 += 32) {
        int ee = e0 + lane;
        if (ee < end) est[ws][lane] = g_csr_idx[ee];
        __syncwarp();
        int cnt = end - e0;
        if (cnt >= 32) {
#pragma unroll
            for (int i = 0; i < 32; i += 8) {
                float v0 = pc[(size_t)est[ws][i + 0] * N_CLS + lane];
                float v1 = pc[(size_t)est[ws][i + 1] * N_CLS + lane];
                float v2 = pc[(size_t)est[ws][i + 2] * N_CLS + lane];
                float v3 = pc[(size_t)est[ws][i + 3] * N_CLS + lane];
                float v4 = pc[(size_t)est[ws][i + 4] * N_CLS + lane];
                float v5 = pc[(size_t)est[ws][i + 5] * N_CLS + lane];
                float v6 = pc[(size_t)est[ws][i + 6] * N_CLS + lane];
                float v7 = pc[(size_t)est[ws][i + 7] * N_CLS + lane];
                acc += ((v0 + v1) + (v2 + v3)) + ((v4 + v5) + (v6 + v7));
            }
        } else {
            int i = 0;
            for (; i + 4 <= cnt; i += 4) {
                float v0 = pc[(size_t)est[ws][i + 0] * N_CLS + lane];
                float v1 = pc[(size_t)est[ws][i + 1] * N_CLS + lane];
                float v2 = pc[(size_t)est[ws][i + 2] * N_CLS + lane];
                float v3 = pc[(size_t)est[ws][i + 3] * N_CLS + lane];
                acc += (v0 + v1) + (v2 + v3);
            }
            for (; i < cnt; i++)
                acc += pc[(size_t)est[ws][i] * N_CLS + lane];
        }
        __syncwarp();
    }

    float fdeg1 = 1.0f + (float)(end - beg);
    float p_new = acc * (1.0f / fdeg1);
    float h_new = p_new * sqrtf(fdeg1);
    float gk = gamma[gi];
    size_t o = (size_t)n * N_CLS + lane;

    if (!LAST) {
        pn[o] = p_new;
        g_acc[o] += gk * h_new;
    } else {
        float v = g_acc[o] + gk * h_new;
        float m = v;
#pragma unroll
        for (int off = 16; off; off >>= 1)
            m = fmaxf(m, __shfl_xor_sync(0xffffffffu, m, off));
        float e = expf(v - m);
        float sum = e;
#pragma unroll
        for (int off = 16; off; off >>= 1)
            sum += __shfl_xor_sync(0xffffffffu, sum, off);
        out[o] = v - m - logf(sum);
    }
}

// ---------------- launch ----------------
extern "C" void kernel_launch(void* const* d_in, const int* in_sizes, int n_in,
                              void* d_out, int out_size) {
    const float* x     = (const float*)d_in[0];
    const void*  eiraw = d_in[1];
    const float* W1    = (const float*)d_in[2];
    const float* b1    = (const float*)d_in[3];
    const float* W2    = (const float*)d_in[4];
    const float* b2    = (const float*)d_in[5];
    const float* gamma = (const float*)d_in[6];
    float*       out   = (float*)d_out;

    // fork a side stream for the (independent) MLP chain
    cudaStream_t s2;
    cudaStreamCreateWithFlags(&s2, cudaStreamNonBlocking);
    cudaEvent_t eFork, eJoin;
    cudaEventCreateWithFlags(&eFork, cudaEventDisableTiming);
    cudaEventCreateWithFlags(&eJoin, cudaEventDisableTiming);

    cudaEventRecord(eFork, 0);
    cudaStreamWaitEvent(s2, eFork, 0);

    // side stream: weight conversion + MLP (independent of edges)
    k_w1cvt<<<(F_IN * HID + 255) / 256, 256, 0, s2>>>(W1);
    k_w2cvt<<<(HID * N_CLS + 255) / 256, 256, 0, s2>>>(W2);
    cudaFuncSetAttribute(k_mlp, cudaFuncAttributeMaxDynamicSharedMemorySize, SMEM_T);
    k_mlp<<<(N_NODES + 127) / 128, 256, SMEM_T, s2>>>(x, b1, b2, gamma);
    cudaEventRecord(eJoin, s2);

    // main stream: edge preprocessing
    k_deg_zero<<<NBLK, 256>>>();
    k_sniff<<<1, 1>>>((const unsigned*)eiraw);
    k_cvt<<<(2 * N_EDGES + 255) / 256, 256>>>(eiraw);
    k_scan1<<<NBLK, 256>>>();
    k_scan2<<<1, 512>>>();
    k_scan3<<<NBLK, 256>>>();
    k_fill<<<(N_EDGES + 255) / 256, 256>>>();

    // join: MLP results needed from here on
    cudaStreamWaitEvent(0, eJoin, 0);
    k_scale<<<(N_NODES * N_CLS / 4 + 255) / 256, 256>>>();

    int cur = 0;
    const int spmvBlocks = (N_NODES + 7) / 8;
    for (int k = 1; k < KSTEPS; k++) {
        k_spmv<false><<<spmvBlocks, 256>>>(cur, k, gamma, out);
        cur ^= 1;
    }
    k_spmv<true><<<spmvBlocks, 256>>>(cur, KSTEPS, gamma, out);
}

// round 9
// speedup vs baseline: 1.1307x; 1.1307x over previous
#include <cuda_runtime.h>
#include <cuda_bf16.h>
#include <cuda_fp16.h>
#include <cstdint>

#define N_NODES 100000
#define F_IN    512
#define HID     256
#define N_CLS   32
#define N_EDGES 3200000
#define KSTEPS  10
#define NBLK    ((N_NODES + 255) / 256)   // 391

// ---------------- device scratch ----------------
__device__ __align__(128) float   g_h0[(size_t)N_NODES * N_CLS];   // fp32 h0 from MLP
__device__ __align__(128) float   g_acc[(size_t)N_NODES * N_CLS];
__device__ __align__(128) __half2 g_p0[(size_t)N_NODES * 16];      // p ping (fp16)
__device__ __align__(128) __half2 g_p1[(size_t)N_NODES * 16];      // p pong (fp16)
__device__ __align__(128) int     g_deg[N_NODES];
__device__ __align__(128) int     g_rowptr[N_NODES + 1];
__device__ __align__(128) int     g_pos[N_NODES];
__device__ __align__(128) int     g_srcv[N_EDGES];
__device__ __align__(128) int     g_dstv[N_EDGES];
__device__ __align__(128) int     g_csr_idx[N_EDGES];
__device__ __align__(128) int     g_bsum[512];
__device__ __align__(128) int     g_boff[512];
__device__ __align__(128) __nv_bfloat16 g_w1t_hi[(size_t)HID * F_IN];
__device__ __align__(128) __nv_bfloat16 g_w1t_lo[(size_t)HID * F_IN];
__device__ __align__(128) __nv_bfloat16 g_w2t_hi[(size_t)N_CLS * HID];
__device__ __align__(128) __nv_bfloat16 g_w2t_lo[(size_t)N_CLS * HID];
__device__ int g_is64;

// ---------------- edge index dtype sniff + convert (+deg count fused) ----------------
__global__ void k_sniff(const unsigned* __restrict__ raw) {
    unsigned orv = 0;
#pragma unroll
    for (int i = 0; i < 16; i++) orv |= raw[2 * i + 1];
    g_is64 = (orv == 0u) ? 1 : 0;
}

__global__ void k_cvt(const void* __restrict__ raw) {
    int i = blockIdx.x * blockDim.x + threadIdx.x;
    if (i >= 2 * N_EDGES) return;
    int v;
    if (g_is64) v = (int)((const long long*)raw)[i];
    else        v = ((const int*)raw)[i];
    if (i < N_EDGES) g_srcv[i] = v;
    else { g_dstv[i - N_EDGES] = v; atomicAdd(&g_deg[v], 1); }
}

__global__ void k_deg_zero() {
    int i = blockIdx.x * blockDim.x + threadIdx.x;
    if (i < N_NODES) g_deg[i] = 0;
}

// ---------------- parallel exclusive scan of g_deg -> g_rowptr/g_pos ----------------
__global__ __launch_bounds__(256) void k_scan1() {
    __shared__ int wsum[8];
    int tid = threadIdx.x;
    int i = blockIdx.x * 256 + tid;
    int v = (i < N_NODES) ? g_deg[i] : 0;
    int x = v;
#pragma unroll
    for (int o = 16; o; o >>= 1) x += __shfl_down_sync(0xffffffffu, x, o);
    if ((tid & 31) == 0) wsum[tid >> 5] = x;
    __syncthreads();
    if (tid < 8) {
        int y = wsum[tid];
#pragma unroll
        for (int o = 4; o; o >>= 1) y += __shfl_down_sync(0xffu, y, o);
        if (tid == 0) g_bsum[blockIdx.x] = y;
    }
}

__global__ __launch_bounds__(512) void k_scan2() {
    __shared__ int wsum[16];
    int tid = threadIdx.x;
    int lane = tid & 31, w = tid >> 5;
    int v = (tid < NBLK) ? g_bsum[tid] : 0;
    int x = v;
#pragma unroll
    for (int o = 1; o < 32; o <<= 1) {
        int t = __shfl_up_sync(0xffffffffu, x, o);
        if (lane >= o) x += t;
    }
    if (lane == 31) wsum[w] = x;
    __syncthreads();
    if (tid < 16) {
        int y = wsum[tid];
#pragma unroll
        for (int o = 1; o < 16; o <<= 1) {
            int t = __shfl_up_sync(0xffffu, y, o);
            if (tid >= o) y += t;
        }
        wsum[tid] = y;
    }
    __syncthreads();
    int pre = (w > 0) ? wsum[w - 1] : 0;
    int excl = pre + x - v;
    g_boff[tid] = excl;
    if (tid == NBLK) g_rowptr[N_NODES] = excl;
}

__global__ __launch_bounds__(256) void k_scan3() {
    __shared__ int wsum[8];
    int tid = threadIdx.x;
    int i = blockIdx.x * 256 + tid;
    int lane = tid & 31, w = tid >> 5;
    int v = (i < N_NODES) ? g_deg[i] : 0;
    int x = v;
#pragma unroll
    for (int o = 1; o < 32; o <<= 1) {
        int t = __shfl_up_sync(0xffffffffu, x, o);
        if (lane >= o) x += t;
    }
    if (lane == 31) wsum[w] = x;
    __syncthreads();
    if (tid < 8) {
        int y = wsum[tid];
#pragma unroll
        for (int o = 1; o < 8; o <<= 1) {
            int t = __shfl_up_sync(0xffu, y, o);
            if (tid >= o) y += t;
        }
        wsum[tid] = y;
    }
    __syncthreads();
    int pre = (w > 0) ? wsum[w - 1] : 0;
    int excl = g_boff[blockIdx.x] + pre + x - v;
    if (i < N_NODES) { g_rowptr[i] = excl; g_pos[i] = excl; }
}

__global__ void k_fill() {
    int e = blockIdx.x * blockDim.x + threadIdx.x;
    if (e >= N_EDGES) return;
    int s = g_srcv[e], d = g_dstv[e];
    int p = atomicAdd(&g_pos[d], 1);
    g_csr_idx[p] = s;
}

// ---------------- weight conversions ----------------
__global__ void k_w1cvt(const float* __restrict__ W1) {
    int i = blockIdx.x * blockDim.x + threadIdx.x;
    if (i >= F_IN * HID) return;
    int k = i / HID, n = i % HID;
    float v = W1[i];
    __nv_bfloat16 h = __float2bfloat16(v);
    g_w1t_hi[(size_t)n * F_IN + k] = h;
    g_w1t_lo[(size_t)n * F_IN + k] = __float2bfloat16(v - __bfloat162float(h));
}

__global__ void k_w2cvt(const float* __restrict__ W2) {
    int i = blockIdx.x * blockDim.x + threadIdx.x;
    if (i >= HID * N_CLS) return;
    int k = i / N_CLS, n = i % N_CLS;
    float v = W2[i];
    __nv_bfloat16 h = __float2bfloat16(v);
    g_w2t_hi[(size_t)n * HID + k] = h;
    g_w2t_lo[(size_t)n * HID + k] = __float2bfloat16(v - __bfloat162float(h));
}

// ---------------- fused MLP: h0 = relu(x@W1+b1)@W2 + b2 ----------------
#define ST1  72
#define ST2  264

#define ASH_O   0u
#define ASL_O   18432u
#define BSH_O   36864u
#define BSL_O   73728u
#define ZHI_O   0u
#define ZLO_O   67584u
#define W2HI_O  135168u
#define W2LO_O  152064u
#define B2_O    168960u
#define BIAS_O  169088u
#define SMEM_T  170112u

#define MMA16816(c, a, b) \
    asm volatile("mma.sync.aligned.m16n8k16.row.col.f32.bf16.bf16.f32 " \
                 "{%0,%1,%2,%3},{%4,%5,%6,%7},{%8,%9},{%0,%1,%2,%3};" \
                 : "+f"((c)[0]), "+f"((c)[1]), "+f"((c)[2]), "+f"((c)[3]) \
                 : "r"((a)[0]), "r"((a)[1]), "r"((a)[2]), "r"((a)[3]), \
                   "r"((b)[0]), "r"((b)[1]))

__device__ __forceinline__ uint32_t pack_hi(float a, float b) {
    __nv_bfloat16 h0 = __float2bfloat16(a), h1 = __float2bfloat16(b);
    return (uint32_t)__bfloat16_as_ushort(h0) | ((uint32_t)__bfloat16_as_ushort(h1) << 16);
}
__device__ __forceinline__ uint32_t pack_lo(float a, float b) {
    __nv_bfloat16 h0 = __float2bfloat16(a), h1 = __float2bfloat16(b);
    float r0 = a - __bfloat162float(h0), r1 = b - __bfloat162float(h1);
    __nv_bfloat16 l0 = __float2bfloat16(r0), l1 = __float2bfloat16(r1);
    return (uint32_t)__bfloat16_as_ushort(l0) | ((uint32_t)__bfloat16_as_ushort(l1) << 16);
}

__global__ __launch_bounds__(256, 1) void k_mlp(const float* __restrict__ x,
                                                const float* __restrict__ b1,
                                                const float* __restrict__ b2,
                                                const float* __restrict__ gamma) {
    extern __shared__ __align__(16) char sm[];
    __nv_bfloat16* as_hi = (__nv_bfloat16*)(sm + ASH_O);
    __nv_bfloat16* as_lo = (__nv_bfloat16*)(sm + ASL_O);
    __nv_bfloat16* bs_hi = (__nv_bfloat16*)(sm + BSH_O);
    __nv_bfloat16* bs_lo = (__nv_bfloat16*)(sm + BSL_O);
    uint32_t* zhi = (uint32_t*)(sm + ZHI_O);
    uint32_t* zlo = (uint32_t*)(sm + ZLO_O);
    __nv_bfloat16* w2hi = (__nv_bfloat16*)(sm + W2HI_O);
    __nv_bfloat16* w2lo = (__nv_bfloat16*)(sm + W2LO_O);
    float* b2s = (float*)(sm + B2_O);
    float* bias_s = (float*)(sm + BIAS_O);

    const int tid = threadIdx.x;
    const int wid = tid >> 5, lane = tid & 31;
    const int gq = lane >> 2, tg = lane & 3;
    const int rowBase = blockIdx.x * 128;
    const int wr = (wid >> 2) * 64, wc = (wid & 3) * 64;

    bias_s[tid] = b1[tid];
    if (tid < N_CLS) b2s[tid] = b2[tid];
    for (int i = tid; i < 1024; i += 256) {
        int n = i >> 5, k8 = (i & 31) * 8;
        *(uint4*)(w2hi + n * ST2 + k8) = *(const uint4*)(g_w2t_hi + n * HID + k8);
        *(uint4*)(w2lo + n * ST2 + k8) = *(const uint4*)(g_w2t_lo + n * HID + k8);
    }

    float acc[4][8][4];
#pragma unroll
    for (int a = 0; a < 4; a++)
#pragma unroll
        for (int b = 0; b < 8; b++)
#pragma unroll
            for (int c = 0; c < 4; c++) acc[a][b][c] = 0.f;

    for (int ch = 0; ch < 8; ch++) {
        const int k0 = ch * 64;
        __syncthreads();
        for (int i = tid; i < 2048; i += 256) {
            int r = i >> 4, cc = (i & 15) * 4;
            float4 v = make_float4(0.f, 0.f, 0.f, 0.f);
            int grow = rowBase + r;
            if (grow < N_NODES)
                v = *(const float4*)(x + (size_t)grow * F_IN + k0 + cc);
            uint2 ph = make_uint2(pack_hi(v.x, v.y), pack_hi(v.z, v.w));
            uint2 pl = make_uint2(pack_lo(v.x, v.y), pack_lo(v.z, v.w));
            *(uint2*)(as_hi + r * ST1 + cc) = ph;
            *(uint2*)(as_lo + r * ST1 + cc) = pl;
        }
        for (int i = tid; i < 2048; i += 256) {
            int n = i >> 3, k8 = (i & 7) * 8;
            size_t gi = (size_t)n * F_IN + k0 + k8;
            *(uint4*)(bs_hi + n * ST1 + k8) = *(const uint4*)(g_w1t_hi + gi);
            *(uint4*)(bs_lo + n * ST1 + k8) = *(const uint4*)(g_w1t_lo + gi);
        }
        __syncthreads();

#pragma unroll
        for (int ks = 0; ks < 4; ks++) {
            const int ko = ks * 16;
            uint32_t ah[4][4], al[4][4];
#pragma unroll
            for (int mt = 0; mt < 4; mt++) {
                int r0 = wr + mt * 16 + gq;
                ah[mt][0] = *(const uint32_t*)(as_hi + r0 * ST1 + ko + 2 * tg);
                ah[mt][1] = *(const uint32_t*)(as_hi + (r0 + 8) * ST1 + ko + 2 * tg);
                ah[mt][2] = *(const uint32_t*)(as_hi + r0 * ST1 + ko + 8 + 2 * tg);
                ah[mt][3] = *(const uint32_t*)(as_hi + (r0 + 8) * ST1 + ko + 8 + 2 * tg);
                al[mt][0] = *(const uint32_t*)(as_lo + r0 * ST1 + ko + 2 * tg);
                al[mt][1] = *(const uint32_t*)(as_lo + (r0 + 8) * ST1 + ko + 2 * tg);
                al[mt][2] = *(const uint32_t*)(as_lo + r0 * ST1 + ko + 8 + 2 * tg);
                al[mt][3] = *(const uint32_t*)(as_lo + (r0 + 8) * ST1 + ko + 8 + 2 * tg);
            }
#pragma unroll
            for (int nt = 0; nt < 8; nt++) {
                int n0 = wc + nt * 8 + gq;
                uint32_t bh[2], bl[2];
                bh[0] = *(const uint32_t*)(bs_hi + n0 * ST1 + ko + 2 * tg);
                bh[1] = *(const uint32_t*)(bs_hi + n0 * ST1 + ko + 8 + 2 * tg);
                bl[0] = *(const uint32_t*)(bs_lo + n0 * ST1 + ko + 2 * tg);
                bl[1] = *(const uint32_t*)(bs_lo + n0 * ST1 + ko + 8 + 2 * tg);
#pragma unroll
                for (int mt = 0; mt < 4; mt++) {
                    MMA16816(acc[mt][nt], ah[mt], bh);
                    MMA16816(acc[mt][nt], ah[mt], bl);
                    MMA16816(acc[mt][nt], al[mt], bh);
                }
            }
        }
    }

    __syncthreads();

    // phase1 epilogue: bias+relu -> z bf16 hi/lo in smem
#pragma unroll
    for (int mt = 0; mt < 4; mt++) {
        int r0 = wr + mt * 16 + gq;
        int r1 = r0 + 8;
#pragma unroll
        for (int nt = 0; nt < 8; nt++) {
            int cl = wc + nt * 8 + 2 * tg;
            float bx = bias_s[cl], by = bias_s[cl + 1];
            float o0 = fmaxf(acc[mt][nt][0] + bx, 0.f);
            float o1 = fmaxf(acc[mt][nt][1] + by, 0.f);
            float o2 = fmaxf(acc[mt][nt][2] + bx, 0.f);
            float o3 = fmaxf(acc[mt][nt][3] + by, 0.f);
            int w0 = r0 * 132 + (cl >> 1);
            int w1 = r1 * 132 + (cl >> 1);
            zhi[w0] = pack_hi(o0, o1); zlo[w0] = pack_lo(o0, o1);
            zhi[w1] = pack_hi(o2, o3); zlo[w1] = pack_lo(o2, o3);
        }
    }
    __syncthreads();

    // phase2: h0 = z @ W2 + b2 ; acc = gamma0*h0
    float acc2[4][4];
#pragma unroll
    for (int a = 0; a < 4; a++)
#pragma unroll
        for (int c = 0; c < 4; c++) acc2[a][c] = 0.f;

    const int rl0 = wid * 16 + gq;
#pragma unroll
    for (int ks = 0; ks < 16; ks++) {
        const int kw = ks * 8 + tg;
        uint32_t ah[4], al[4];
        ah[0] = zhi[rl0 * 132 + kw];
        ah[1] = zhi[(rl0 + 8) * 132 + kw];
        ah[2] = zhi[rl0 * 132 + kw + 4];
        ah[3] = zhi[(rl0 + 8) * 132 + kw + 4];
        al[0] = zlo[rl0 * 132 + kw];
        al[1] = zlo[(rl0 + 8) * 132 + kw];
        al[2] = zlo[rl0 * 132 + kw + 4];
        al[3] = zlo[(rl0 + 8) * 132 + kw + 4];
#pragma unroll
        for (int nt = 0; nt < 4; nt++) {
            int n0 = nt * 8 + gq;
            uint32_t bh[2], bl[2];
            bh[0] = *(const uint32_t*)(w2hi + n0 * ST2 + ks * 16 + 2 * tg);
            bh[1] = *(const uint32_t*)(w2hi + n0 * ST2 + ks * 16 + 8 + 2 * tg);
            bl[0] = *(const uint32_t*)(w2lo + n0 * ST2 + ks * 16 + 2 * tg);
            bl[1] = *(const uint32_t*)(w2lo + n0 * ST2 + ks * 16 + 8 + 2 * tg);
            MMA16816(acc2[nt], ah, bh);
            MMA16816(acc2[nt], ah, bl);
            MMA16816(acc2[nt], al, bh);
        }
    }

    float g0 = gamma[0];
    int row0 = rowBase + rl0, row1 = row0 + 8;
#pragma unroll
    for (int nt = 0; nt < 4; nt++) {
        int cl = nt * 8 + 2 * tg;
        float bx = b2s[cl], by = b2s[cl + 1];
        if (row0 < N_NODES) {
            float hx = acc2[nt][0] + bx, hy = acc2[nt][1] + by;
            *(float2*)(g_h0 + (size_t)row0 * N_CLS + cl) = make_float2(hx, hy);
            *(float2*)(g_acc + (size_t)row0 * N_CLS + cl) = make_float2(g0 * hx, g0 * hy);
        }
        if (row1 < N_NODES) {
            float hx = acc2[nt][2] + bx, hy = acc2[nt][3] + by;
            *(float2*)(g_h0 + (size_t)row1 * N_CLS + cl) = make_float2(hx, hy);
            *(float2*)(g_acc + (size_t)row1 * N_CLS + cl) = make_float2(g0 * hx, g0 * hy);
        }
    }
}

// ---------------- scale: p0 = fp16(dinv * h0) ----------------
__global__ void k_scale() {
    int i = blockIdx.x * blockDim.x + threadIdx.x;   // one half2 (2 classes)
    if (i >= N_NODES * 16) return;
    int n = i >> 4;
    float di = rsqrtf(1.0f + (float)g_deg[n]);
    float2 v = *(float2*)(g_h0 + (size_t)i * 2);
    g_p0[i] = __floats2half2_rn(v.x * di, v.y * di);
}

// ---------------- SpMV step on p = dinv*h (fp16 state, fp32 math) ----------------
// warp per node; lanes 0-15 = edge i, lanes 16-31 = edge i+1; each lane owns 2 classes
template <bool LAST>
__global__ __launch_bounds__(256) void k_spmv(int cur, int gi,
                                              const float* __restrict__ gamma,
                                              float* __restrict__ out) {
    __shared__ int est[8][32];
    const __half2* pc = cur ? g_p1 : g_p0;
    __half2* pn = cur ? g_p0 : g_p1;

    const int ws = threadIdx.x >> 5;
    int n = (blockIdx.x * blockDim.x + threadIdx.x) >> 5;
    int lane = threadIdx.x & 31;
    if (n >= N_NODES) return;
    const int c16 = lane & 15;        // class pair index
    const int hsel = lane >> 4;       // which of the 2 edges this half-warp handles
    int beg = g_rowptr[n], end = g_rowptr[n + 1];

    float2 acc = make_float2(0.f, 0.f);

    for (int e0 = beg; e0 < end; e0 += 32) {
        int ee = e0 + lane;
        if (ee < end) est[ws][lane] = g_csr_idx[ee];
        __syncwarp();
        int cnt = end - e0; if (cnt > 32) cnt = 32;
        int i = 0;
        for (; i + 8 <= cnt; i += 8) {
            int s0 = est[ws][i + 0 + hsel];
            int s1 = est[ws][i + 2 + hsel];
            int s2 = est[ws][i + 4 + hsel];
            int s3 = est[ws][i + 6 + hsel];
            float2 v0 = __half22float2(pc[(size_t)s0 * 16 + c16]);
            float2 v1 = __half22float2(pc[(size_t)s1 * 16 + c16]);
            float2 v2 = __half22float2(pc[(size_t)s2 * 16 + c16]);
            float2 v3 = __half22float2(pc[(size_t)s3 * 16 + c16]);
            acc.x += (v0.x + v1.x) + (v2.x + v3.x);
            acc.y += (v0.y + v1.y) + (v2.y + v3.y);
        }
        for (; i + 2 <= cnt; i += 2) {
            int s0 = est[ws][i + hsel];
            float2 v0 = __half22float2(pc[(size_t)s0 * 16 + c16]);
            acc.x += v0.x; acc.y += v0.y;
        }
        if (i < cnt && hsel == 0) {
            int s0 = est[ws][i];
            float2 v0 = __half22float2(pc[(size_t)s0 * 16 + c16]);
            acc.x += v0.x; acc.y += v0.y;
        }
        __syncwarp();
    }

    // combine the two half-warps (same classes, disjoint edges)
    acc.x += __shfl_xor_sync(0xffffffffu, acc.x, 16);
    acc.y += __shfl_xor_sync(0xffffffffu, acc.y, 16);

    // self loop
    float2 ps = __half22float2(pc[(size_t)n * 16 + c16]);
    acc.x += ps.x; acc.y += ps.y;

    float fdeg1 = 1.0f + (float)(end - beg);
    float inv = 1.0f / fdeg1;
    float sq = sqrtf(fdeg1);
    float px = acc.x * inv, py = acc.y * inv;
    float hx = px * sq,     hy = py * sq;
    float gk = gamma[gi];
    size_t of = (size_t)n * N_CLS + 2 * c16;

    if (!LAST) {
        if (lane < 16) {
            pn[(size_t)n * 16 + c16] = __floats2half2_rn(px, py);
            float2 a = *(float2*)(g_acc + of);
            a.x += gk * hx; a.y += gk * hy;
            *(float2*)(g_acc + of) = a;
        }
    } else {
        float2 a = *(float2*)(g_acc + of);
        float vx = a.x + gk * hx;
        float vy = a.y + gk * hy;
        float m = fmaxf(vx, vy);
#pragma unroll
        for (int off = 8; off; off >>= 1)
            m = fmaxf(m, __shfl_xor_sync(0xffffffffu, m, off));
        float s = expf(vx - m) + expf(vy - m);
#pragma unroll
        for (int off = 8; off; off >>= 1)
            s += __shfl_xor_sync(0xffffffffu, s, off);
        if (lane < 16) {
            float l = logf(s);
            *(float2*)(out + of) = make_float2(vx - m - l, vy - m - l);
        }
    }
}

// ---------------- launch ----------------
extern "C" void kernel_launch(void* const* d_in, const int* in_sizes, int n_in,
                              void* d_out, int out_size) {
    const float* x     = (const float*)d_in[0];
    const void*  eiraw = d_in[1];
    const float* W1    = (const float*)d_in[2];
    const float* b1    = (const float*)d_in[3];
    const float* W2    = (const float*)d_in[4];
    const float* b2    = (const float*)d_in[5];
    const float* gamma = (const float*)d_in[6];
    float*       out   = (float*)d_out;

    // fork a side stream for the (independent) MLP chain
    cudaStream_t s2;
    cudaStreamCreateWithFlags(&s2, cudaStreamNonBlocking);
    cudaEvent_t eFork, eJoin;
    cudaEventCreateWithFlags(&eFork, cudaEventDisableTiming);
    cudaEventCreateWithFlags(&eJoin, cudaEventDisableTiming);

    cudaEventRecord(eFork, 0);
    cudaStreamWaitEvent(s2, eFork, 0);

    // side stream: weight conversion + MLP (independent of edges)
    k_w1cvt<<<(F_IN * HID + 255) / 256, 256, 0, s2>>>(W1);
    k_w2cvt<<<(HID * N_CLS + 255) / 256, 256, 0, s2>>>(W2);
    cudaFuncSetAttribute(k_mlp, cudaFuncAttributeMaxDynamicSharedMemorySize, SMEM_T);
    k_mlp<<<(N_NODES + 127) / 128, 256, SMEM_T, s2>>>(x, b1, b2, gamma);
    cudaEventRecord(eJoin, s2);

    // main stream: edge preprocessing
    k_deg_zero<<<NBLK, 256>>>();
    k_sniff<<<1, 1>>>((const unsigned*)eiraw);
    k_cvt<<<(2 * N_EDGES + 255) / 256, 256>>>(eiraw);
    k_scan1<<<NBLK, 256>>>();
    k_scan2<<<1, 512>>>();
    k_scan3<<<NBLK, 256>>>();
    k_fill<<<(N_EDGES + 255) / 256, 256>>>();

    // join: MLP results needed from here on
    cudaStreamWaitEvent(0, eJoin, 0);
    k_scale<<<(N_NODES * 16 + 255) / 256, 256>>>();

    int cur = 0;
    const int spmvBlocks = (N_NODES + 7) / 8;
    for (int k = 1; k < KSTEPS; k++) {
        k_spmv<false><<<spmvBlocks, 256>>>(cur, k, gamma, out);
        cur ^= 1;
    }
    k_spmv<true><<<spmvBlocks, 256>>>(cur, KSTEPS, gamma, out);
}